// round 12
// baseline (speedup 1.0000x reference)
#include <cuda_runtime.h>
#include <cuda_fp16.h>
#include <cstdint>
#include <cstddef>

#define N_NODES 100000
#define N_EDGES 600000
#define DMODEL  128
#define NREL    50
#define N_PAD   100096          // 782 tiles * 128

// Scratch
__device__ float  g_T[(size_t)4 * N_NODES * DMODEL];   // transformed features [4][N][128]
__device__ float  g_G[4 * N_NODES];                    // gate pre-activations
__device__ __half g_Wh4[4 * 128 * 136];                // fp16 weights, padded pitch 136
// CSR-by-target scratch
__device__ int g_cnt[N_NODES];
__device__ int g_fill[N_NODES];
__device__ int g_start[N_NODES];
__device__ int g_perm[N_EDGES];
__device__ int g_cursor[1];

#define MMA_F16(c, a0, a1, a2, a3, b0, b1)                                   \
    asm volatile("mma.sync.aligned.m16n8k16.row.col.f32.f16.f16.f32 "        \
                 "{%0,%1,%2,%3}, {%4,%5,%6,%7}, {%8,%9}, {%0,%1,%2,%3};"     \
                 : "+f"(c[0]), "+f"(c[1]), "+f"(c[2]), "+f"(c[3])            \
                 : "r"(a0), "r"(a1), "r"(a2), "r"(a3), "r"(b0), "r"(b1))

__device__ __forceinline__ uint32_t smem_u32(const void* p) {
    uint32_t a;
    asm("{ .reg .u64 t; cvta.to.shared.u64 t, %1; cvt.u32.u64 %0, t; }" : "=r"(a) : "l"(p));
    return a;
}
__device__ __forceinline__ void cpa16(uint32_t dst, const void* src) {
    asm volatile("cp.async.cg.shared.global [%0], [%1], 16;" :: "r"(dst), "l"(src));
}
#define CPA_COMMIT() asm volatile("cp.async.commit_group;" ::: "memory")
#define CPA_WAIT0()  asm volatile("cp.async.wait_group 0;" ::: "memory")

// ---- CSR build ----
__global__ __launch_bounds__(256) void zero_kernel() {
    int i = blockIdx.x * 256 + threadIdx.x;
    if (i < N_NODES) { g_cnt[i] = 0; g_fill[i] = 0; }
    if (i == 0) g_cursor[0] = 0;
}

__global__ __launch_bounds__(256) void hist_kernel(const int* __restrict__ eidx) {
    int e = blockIdx.x * 256 + threadIdx.x;
    if (e < N_EDGES) atomicAdd(&g_cnt[eidx[N_EDGES + e]], 1);
}

__global__ __launch_bounds__(256) void alloc_kernel() {
    int n = blockIdx.x * 256 + threadIdx.x;
    int lane = threadIdx.x & 31, warp = threadIdx.x >> 5;
    int c = (n < N_NODES) ? g_cnt[n] : 0;
    int incl = c;
    #pragma unroll
    for (int off = 1; off < 32; off <<= 1) {
        int y = __shfl_up_sync(0xffffffff, incl, off);
        if (lane >= off) incl += y;
    }
    __shared__ int wsum[8], wbase[8], bbase;
    if (lane == 31) wsum[warp] = incl;
    __syncthreads();
    if (threadIdx.x == 0) {
        int s = 0;
        #pragma unroll
        for (int w = 0; w < 8; w++) { wbase[w] = s; s += wsum[w]; }
        bbase = atomicAdd(&g_cursor[0], s);
    }
    __syncthreads();
    if (n < N_NODES) g_start[n] = bbase + wbase[warp] + (incl - c);
}

__global__ __launch_bounds__(256) void scatter_kernel(const int* __restrict__ eidx) {
    int e = blockIdx.x * 256 + threadIdx.x;
    if (e < N_EDGES) {
        int tgt = eidx[N_EDGES + e];
        int pos = g_start[tgt] + atomicAdd(&g_fill[tgt], 1);
        g_perm[pos] = e;
    }
}

// ---- weights -> fp16, padded pitch-136 layout ----
__global__ __launch_bounds__(256) void prep_weights_kernel(
    const float* __restrict__ W0, const float* __restrict__ W1,
    const float* __restrict__ W2, const float* __restrict__ W3)
{
    for (int e = blockIdx.x * 256 + threadIdx.x; e < 4 * 128 * 64; e += gridDim.x * 256) {
        int t = e >> 13, r = (e >> 6) & 127, cp = e & 63;
        const float* W = (t == 0) ? W0 : (t == 1) ? W1 : (t == 2) ? W2 : W3;
        float2 v = reinterpret_cast<const float2*>(W)[r * 64 + cp];
        __half2 h = __float22half2_rn(v);
        *reinterpret_cast<__half2*>(&g_Wh4[t * 128 * 136 + r * 136 + 2 * cp]) = h;
    }
}

// ---- transform: 512 threads; fused fp32 gate dots; cp.async double-buffered W ----
// smem: Sf fp32 [128][132] (67584) + Ah half [128][136] (34816) + W0 + W1
#define SM_SF  0
#define SM_AH  67584
#define SM_W0  (SM_AH + 34816)
#define SM_W1  (SM_W0 + 34816)
#define SM_TOT (SM_W1 + 34816)

__global__ __launch_bounds__(512, 1) void transform_kernel(
    const float* __restrict__ inp,
    const float* __restrict__ G0, const float* __restrict__ G1,
    const float* __restrict__ G2, const float* __restrict__ G3)
{
    extern __shared__ char sm[];
    float*  Sf  = (float*)(sm + SM_SF);
    __half* Ah  = (__half*)(sm + SM_AH);
    __half* Wb0 = (__half*)(sm + SM_W0);
    __half* Wb1 = (__half*)(sm + SM_W1);
    const uint32_t sSf = smem_u32(Sf);
    const uint32_t sW0 = smem_u32(Wb0);
    const uint32_t sW1 = smem_u32(Wb1);

    const int tid  = threadIdx.x;
    const int warp = tid >> 5, lane = tid & 31;
    const int gid  = lane >> 2, tg = lane & 3;
    const int m0   = blockIdx.x * 128;
    const int lrow = tid & 127;
    const int lch0 = tid >> 7;              // 0..3

    // Issue fp32 A tile (row-clamped; garbage rows never stored) + W[0] tile
    {
        int gr = m0 + lrow; if (gr >= N_NODES) gr = N_NODES - 1;
        const float* src = inp + (size_t)gr * DMODEL;
        for (int ch = lch0; ch < 32; ch += 4)
            cpa16(sSf + lrow * 528 + ch * 16, src + ch * 4);
        for (int ch = lch0; ch < 17; ch += 4)
            cpa16(sW0 + lrow * 272 + ch * 16, g_Wh4 + (lrow * 136 + ch * 8));
    }
    CPA_COMMIT();
    CPA_WAIT0();
    __syncthreads();

    // Convert Sf -> Ah (half) and compute 4 gate dots per node (fp32)
    for (int idx = tid; idx < 128 * 64; idx += 512) {
        int row = idx >> 6, cp = idx & 63;
        float2 v = make_float2(Sf[row * 132 + 2 * cp], Sf[row * 132 + 2 * cp + 1]);
        *reinterpret_cast<__half2*>(&Ah[row * 136 + 2 * cp]) = __float22half2_rn(v);
    }
    {
        int node = tid >> 2, ty = tid & 3;
        const float* gw = (ty == 0) ? G0 : (ty == 1) ? G1 : (ty == 2) ? G2 : G3;
        float s = 0.f;
        #pragma unroll 8
        for (int k = 0; k < 128; k++) s += Sf[node * 132 + k] * __ldg(&gw[k]);
        int gr = m0 + node;
        if (gr < N_NODES) g_G[ty * N_NODES + gr] = s;
    }
    __syncthreads();

    const int mrow = (warp >> 1) * 16;
    const int nc0  = (warp & 1) * 64;

    #pragma unroll
    for (int t = 0; t < 4; t++) {
        if (t < 3) {
            uint32_t dstW = ((t + 1) & 1) ? sW1 : sW0;
            const __half* srcW = g_Wh4 + (t + 1) * 128 * 136;
            for (int ch = lch0; ch < 17; ch += 4)
                cpa16(dstW + lrow * 272 + ch * 16, srcW + (lrow * 136 + ch * 8));
            CPA_COMMIT();
        }

        const __half* Wh = (t & 1) ? Wb1 : Wb0;
        float acc[8][4];
        #pragma unroll
        for (int j = 0; j < 8; j++) { acc[j][0] = acc[j][1] = acc[j][2] = acc[j][3] = 0.f; }

        #pragma unroll
        for (int k0 = 0; k0 < 128; k0 += 16) {
            unsigned a0 = *(const unsigned*)&Ah[(mrow + gid)     * 136 + k0 + 2 * tg];
            unsigned a1 = *(const unsigned*)&Ah[(mrow + gid + 8) * 136 + k0 + 2 * tg];
            unsigned a2 = *(const unsigned*)&Ah[(mrow + gid)     * 136 + k0 + 2 * tg + 8];
            unsigned a3 = *(const unsigned*)&Ah[(mrow + gid + 8) * 136 + k0 + 2 * tg + 8];
            #pragma unroll
            for (int j = 0; j < 8; j++) {
                unsigned b0 = *(const unsigned*)&Wh[(nc0 + j * 8 + gid) * 136 + k0 + 2 * tg];
                unsigned b1 = *(const unsigned*)&Wh[(nc0 + j * 8 + gid) * 136 + k0 + 2 * tg + 8];
                MMA_F16(acc[j], a0, a1, a2, a3, b0, b1);
            }
        }

        float* Tout = g_T + (size_t)t * N_NODES * DMODEL;
        int r0 = m0 + mrow + gid, r1 = r0 + 8;
        #pragma unroll
        for (int j = 0; j < 8; j++) {
            int col = nc0 + j * 8 + 2 * tg;
            if (r0 < N_NODES)
                *reinterpret_cast<float2*>(&Tout[(size_t)r0 * DMODEL + col]) =
                    make_float2(acc[j][0], acc[j][1]);
            if (r1 < N_NODES)
                *reinterpret_cast<float2*>(&Tout[(size_t)r1 * DMODEL + col]) =
                    make_float2(acc[j][2], acc[j][3]);
        }

        CPA_WAIT0();
        __syncthreads();
    }
}

// ---- gather: one warp per target node; register accumulation; one STG per lane ----
__global__ __launch_bounds__(256) void gather_kernel(
    const int* __restrict__ deprel, const int* __restrict__ deparc,
    const int* __restrict__ eidx,
    const float* __restrict__ b_in, const float* __restrict__ b_out,
    const float* __restrict__ bg_in, const float* __restrict__ bg_out,
    float* __restrict__ out)
{
    int n = (int)((blockIdx.x * blockDim.x + threadIdx.x) >> 5);
    if (n >= N_NODES) return;
    int lane = threadIdx.x & 31;

    int beg = g_start[n];
    int deg = g_cnt[n];
    float4 acc = make_float4(0.f, 0.f, 0.f, 0.f);
    const float4* T4 = reinterpret_cast<const float4*>(g_T);
    const float4* bi4 = reinterpret_cast<const float4*>(b_in);
    const float4* bo4 = reinterpret_cast<const float4*>(b_out);

    for (int base = 0; base < deg; base += 32) {
        int m = deg - base; if (m > 32) m = 32;
        int t = 0, rel = 0, src = 0;
        float gv = 0.f;
        if (lane < m) {
            int e = g_perm[beg + base + lane];
            t   = __ldg(&deparc[e]);
            rel = __ldg(&deprel[e]);
            src = __ldg(&eidx[e]);
            float gp = g_G[t * N_NODES + src];
            if (t == 0)      gp += __ldg(&bg_in[rel]);
            else if (t == 1) gp += __ldg(&bg_out[rel]);
            gv = 1.f / (1.f + __expf(-gp));
        }
        for (int i = 0; i < m; i++) {
            int   ti = __shfl_sync(0xffffffff, t,   i);
            int   si = __shfl_sync(0xffffffff, src, i);
            int   ri = __shfl_sync(0xffffffff, rel, i);
            float gi = __shfl_sync(0xffffffff, gv,  i);
            float4 v = T4[((size_t)ti * N_NODES + si) * 32 + lane];
            float4 b = make_float4(0.f, 0.f, 0.f, 0.f);
            if (ti == 0)      b = bi4[ri * 32 + lane];
            else if (ti == 1) b = bo4[ri * 32 + lane];
            acc.x += (v.x + b.x) * gi;
            acc.y += (v.y + b.y) * gi;
            acc.z += (v.z + b.z) * gi;
            acc.w += (v.w + b.w) * gi;
        }
    }
    reinterpret_cast<float4*>(out)[(size_t)n * 32 + lane] = acc;
}

extern "C" void kernel_launch(void* const* d_in, const int* in_sizes, int n_in,
                              void* d_out, int out_size)
{
    const float* inp       = (const float*)d_in[0];
    const int*   deprel    = (const int*)d_in[1];
    const int*   deparc    = (const int*)d_in[2];
    const int*   eidx      = (const int*)d_in[3];
    const float* V_in      = (const float*)d_in[4];
    const float* b_in      = (const float*)d_in[5];
    const float* V_in_g    = (const float*)d_in[6];
    const float* b_in_g    = (const float*)d_in[7];
    const float* V_out     = (const float*)d_in[8];
    const float* b_out     = (const float*)d_in[9];
    const float* V_out_g   = (const float*)d_in[10];
    const float* b_out_g   = (const float*)d_in[11];
    const float* W_self    = (const float*)d_in[12];
    const float* W_self_g  = (const float*)d_in[13];
    const float* W_norel   = (const float*)d_in[14];
    const float* W_norel_g = (const float*)d_in[15];
    float* out = (float*)d_out;

    cudaFuncSetAttribute(transform_kernel,
                         cudaFuncAttributeMaxDynamicSharedMemorySize, SM_TOT);

    // CSR build (independent of transform; stream-ordered)
    zero_kernel<<<(N_NODES + 255) / 256, 256>>>();
    hist_kernel<<<(N_EDGES + 255) / 256, 256>>>(eidx);
    alloc_kernel<<<(N_NODES + 255) / 256, 256>>>();
    scatter_kernel<<<(N_EDGES + 255) / 256, 256>>>(eidx);

    prep_weights_kernel<<<16, 256>>>(V_in, V_out, W_self, W_norel);

    transform_kernel<<<N_PAD / 128, 512, SM_TOT>>>(
        inp, V_in_g, V_out_g, W_self_g, W_norel_g);

    gather_kernel<<<(N_NODES * 32 + 255) / 256, 256>>>(
        deprel, deparc, eidx, b_in, b_out, b_in_g, b_out_g, out);
}